// round 12
// baseline (speedup 1.0000x reference)
#include <cuda_runtime.h>

// Problem constants
#define Bv 8
#define Nv 128
#define Dv 256
#define Hv 128
#define Kv 8

// Scratch (allocation-free rule: __device__ globals)
__device__ float g_Ai [Bv * Nv * Hv];   // [b*N+i][h]        : E @ W1a^T
__device__ float g_AjT[Bv * Hv * Nv];   // [b][h][j]         : (E @ W1b^T) + b1
__device__ float g_Wq [Hv * Kv];        // [h][k]
__device__ float g_bq [Kv];

// ---------------------------------------------------------------------------
// Kernel 1 (fused with k2): GEMM for both W1 halves + tiny Wq/bq blocks.
// Register double-buffered global loads; PLAIN scalar FFMA inner loop
// (fma.rn.f32x2 reverted: 3x64-bit operands hit RF-bank rt, no net gain).
// ---------------------------------------------------------------------------
__global__ void __launch_bounds__(128) k1_fused(const float* __restrict__ E,
                                                const float* __restrict__ W1,
                                                const float* __restrict__ b1,
                                                const float* __restrict__ W2,
                                                const float* __restrict__ b2,
                                                const float* __restrict__ q)
{
    __shared__ float Es[2][32 * 18];   // [buf][k][m], m-pad 18
    __shared__ float Ws[2][32 * 68];   // [buf][k][c], c-pad 68
    __shared__ float qs[Dv];

    const int blk = blockIdx.x;
    const int tid = threadIdx.x;

    if (blk >= 256) {
        // ---- k2: Wq[h][k] = sum_d W2[d][h]*q[k][d], bq[k] = b2·q[k] ----
        const int k = blk - 256;
        for (int d = tid; d < Dv; d += 128) qs[d] = q[k * Dv + d];
        __syncthreads();
        float s = 0.0f;
#pragma unroll 16
        for (int d = 0; d < Dv; d++) s = fmaf(W2[d * Hv + tid], qs[d], s);
        g_Wq[tid * Kv + k] = s;
        if (tid == 0) {
            float t = 0.0f;
            for (int d = 0; d < Dv; d++) t = fmaf(b2[d], qs[d], t);
            g_bq[k] = t;
        }
        return;
    }

    // ---- GEMM block ----
    const int ct = blk & 3;               // col tile (64 cols)
    const int mt = blk >> 2;              // row tile (16 rows), 0..63
    const int tx = tid & 15;              // cols 4*tx
    const int ty = tid >> 4;              // rows 2*ty (0..7)
    const int row0  = mt * 16;
    const bool isB  = (ct >= 2);
    const int hbase = (isB ? (ct - 2) : ct) * 64;
    const int dofs  = isB ? Dv : 0;

    const int ek = tid & 31;              // k within chunk
    const int em = tid >> 5;              // +4u -> m (E), c (W) base

    float eR[4], wR[16];
    {
        const float* Ep = E + (long)(row0 + em) * Dv + ek;
#pragma unroll
        for (int u = 0; u < 4; u++) eR[u] = Ep[u * 4 * Dv];
        const float* Wp = W1 + (long)(hbase + em) * (2 * Dv) + dofs + ek;
#pragma unroll
        for (int u = 0; u < 16; u++) wR[u] = Wp[u * 4 * (2 * Dv)];
    }

    float acc[2][4];
#pragma unroll
    for (int r = 0; r < 2; r++)
#pragma unroll
        for (int c = 0; c < 4; c++) acc[r][c] = 0.0f;

    for (int c = 0; c < 8; c++) {
        const int buf = c & 1;
#pragma unroll
        for (int u = 0; u < 4; u++)  Es[buf][ek * 18 + em + 4 * u] = eR[u];
#pragma unroll
        for (int u = 0; u < 16; u++) Ws[buf][ek * 68 + em + 4 * u] = wR[u];
        __syncthreads();

        if (c < 7) {
            const int kc = (c + 1) * 32;
            const float* Ep = E + (long)(row0 + em) * Dv + kc + ek;
#pragma unroll
            for (int u = 0; u < 4; u++) eR[u] = Ep[u * 4 * Dv];
            const float* Wp = W1 + (long)(hbase + em) * (2 * Dv) + dofs + kc + ek;
#pragma unroll
            for (int u = 0; u < 16; u++) wR[u] = Wp[u * 4 * (2 * Dv)];
        }

#pragma unroll
        for (int k = 0; k < 32; k++) {
            float2 av = *(const float2*)&Es[buf][k * 18 + 2 * ty];
            float4 bv = *(const float4*)&Ws[buf][k * 68 + 4 * tx];
            acc[0][0] = fmaf(av.x, bv.x, acc[0][0]);
            acc[0][1] = fmaf(av.x, bv.y, acc[0][1]);
            acc[0][2] = fmaf(av.x, bv.z, acc[0][2]);
            acc[0][3] = fmaf(av.x, bv.w, acc[0][3]);
            acc[1][0] = fmaf(av.y, bv.x, acc[1][0]);
            acc[1][1] = fmaf(av.y, bv.y, acc[1][1]);
            acc[1][2] = fmaf(av.y, bv.z, acc[1][2]);
            acc[1][3] = fmaf(av.y, bv.w, acc[1][3]);
        }
        __syncthreads();
    }

#pragma unroll
    for (int r = 0; r < 2; r++) {
        const int grow = row0 + 2 * ty + r;        // b*N + i
#pragma unroll
        for (int cc = 0; cc < 4; cc++) {
            const int h = hbase + 4 * tx + cc;
            if (!isB) {
                g_Ai[grow * Hv + h] = acc[r][cc];
            } else {
                const int b = grow >> 7, i = grow & 127;
                g_AjT[(b * Hv + h) * Nv + i] = acc[r][cc] + b1[h];
            }
        }
    }
}

// ---------------------------------------------------------------------------
// Kernel 3 (dominant): fused relu-GEMV + sigmoid + diagonal mask.
// R12: R4 shape (128 blocks, 16i x 64j, 1i x 4j x 8k per thread) with PLAIN
// scalar FFMA (FFMA2 reverted — it was the R9 regression), plus R11's
// one-iteration software pipeline and bank-spread sAi.
// ---------------------------------------------------------------------------
__global__ void __launch_bounds__(256, 1) k3_main(float* __restrict__ out)
{
    __shared__ float sAi[16 * 132];   // [i][h], stride 132 (bank-spread)
    __shared__ float sAj[Hv][64];     // [h][j] (b1 pre-added) 32 KB
    __shared__ float sWq[Hv * Kv];    // 4 KB
    __shared__ float sBq[Kv];

    const int jt = blockIdx.x, it = blockIdx.y, b = blockIdx.z;
    const int j0 = jt * 64, i0 = it * 16;
    const int tid = threadIdx.x;

    for (int idx = tid; idx < Hv * 64; idx += 256) {
        int h = idx >> 6, j = idx & 63;
        sAj[h][j] = g_AjT[(b * Hv + h) * Nv + j0 + j];
    }
    for (int idx = tid; idx < 16 * Hv; idx += 256) {
        int i = idx >> 7, h = idx & 127;
        sAi[i * 132 + h] = g_Ai[(b * Nv + i0 + i) * Hv + h];
    }
    for (int idx = tid; idx < Hv * Kv; idx += 256) sWq[idx] = g_Wq[idx];
    if (tid < Kv) sBq[tid] = g_bq[tid];
    __syncthreads();

    const int i  = tid >> 4;          // 0..15
    const int jb = (tid & 15) * 4;    // 0,4,...,60

    float acc[4][Kv];
#pragma unroll
    for (int jj = 0; jj < 4; jj++)
#pragma unroll
        for (int k = 0; k < Kv; k++) acc[jj][k] = 0.0f;

    // ---- software pipeline: prefetch h=0 ----
    float  ai_c = sAi[i * 132];
    float4 aj_c = *(const float4*)&sAj[0][jb];
    float4 w0_c = *(const float4*)&sWq[0];
    float4 w1_c = *(const float4*)&sWq[4];

#pragma unroll 4
    for (int h = 0; h < Hv; h++) {
        // next iteration's loads first (wrap at end: redundant, harmless)
        const int hn = (h + 1) & 127;
        float  ai_n = sAi[i * 132 + hn];
        float4 aj_n = *(const float4*)&sAj[hn][jb];
        float4 w0_n = *(const float4*)&sWq[hn * Kv];
        float4 w1_n = *(const float4*)&sWq[hn * Kv + 4];

        float s[4];
        s[0] = fmaxf(ai_c + aj_c.x, 0.0f);
        s[1] = fmaxf(ai_c + aj_c.y, 0.0f);
        s[2] = fmaxf(ai_c + aj_c.z, 0.0f);
        s[3] = fmaxf(ai_c + aj_c.w, 0.0f);
        float w[8] = {w0_c.x, w0_c.y, w0_c.z, w0_c.w,
                      w1_c.x, w1_c.y, w1_c.z, w1_c.w};
#pragma unroll
        for (int jj = 0; jj < 4; jj++)
#pragma unroll
            for (int k = 0; k < Kv; k++)
                acc[jj][k] = fmaf(s[jj], w[k], acc[jj][k]);

        ai_c = ai_n; aj_c = aj_n; w0_c = w0_n; w1_c = w1_n;
    }

    const int gi = i0 + i;
    const int dj = gi - (j0 + jb);    // diagonal lane within our 4 j's, if any

#pragma unroll
    for (int k = 0; k < Kv; k++) {
        float bk = sBq[k];
        float4 v;
        v.x = __fdividef(1.0f, 1.0f + __expf(-(acc[0][k] + bk)));
        v.y = __fdividef(1.0f, 1.0f + __expf(-(acc[1][k] + bk)));
        v.z = __fdividef(1.0f, 1.0f + __expf(-(acc[2][k] + bk)));
        v.w = __fdividef(1.0f, 1.0f + __expf(-(acc[3][k] + bk)));
        if      (dj == 0) v.x = 0.0f;
        else if (dj == 1) v.y = 0.0f;
        else if (dj == 2) v.z = 0.0f;
        else if (dj == 3) v.w = 0.0f;
        *(float4*)&out[(((b * Kv + k) * Nv + gi) << 7) + j0 + jb] = v;
    }
}

// ---------------------------------------------------------------------------
extern "C" void kernel_launch(void* const* d_in, const int* in_sizes, int n_in,
                              void* d_out, int out_size)
{
    const float* E  = (const float*)d_in[0];
    const float* W1 = (const float*)d_in[1];
    const float* b1 = (const float*)d_in[2];
    const float* W2 = (const float*)d_in[3];
    const float* b2 = (const float*)d_in[4];
    const float* q  = (const float*)d_in[5];
    float* out = (float*)d_out;

    k1_fused<<<264, 128>>>(E, W1, b1, W2, b2, q);
    k3_main<<<dim3(2, 8, 8), 256>>>(out);
}